// round 3
// baseline (speedup 1.0000x reference)
#include <cuda_runtime.h>
#include <cuda_bf16.h>
#include <cstdint>

#define BATCH 8192
#define DIM   2048
#define EPSV  1e-8f
#define MARGINV 0.2f

static constexpr int THREADS = 256;
static constexpr int ROW_F4  = DIM / 4;   // 512

__device__ float2 g_loss[BATCH];
__device__ int    g_is32;      // 1 if cand arrays are int32, 0 if int64
__device__ unsigned g_done;    // last-block-arrives counter (reset by last block)

__device__ __forceinline__ float dot4(float4 a, float4 b) {
    return a.x * b.x + a.y * b.y + a.z * b.z + a.w * b.w;
}

// Probe index dtype with ONE warp / one load round-trip.
// For int64 data (values < 8192) every odd 32-bit word is 0.
// For int32 data odd words are random candidate ids in [0,8191]:
// P(all 64 sampled words == 0) ~ 8192^-64 ~ 0.
__global__ void detect_dtype(const unsigned* __restrict__ c0,
                             const unsigned* __restrict__ c1) {
    const int t = threadIdx.x;               // 32 threads
    unsigned any = c0[2 * t + 1] | c1[2 * t + 1];   // words 1..63 (odd)
    #pragma unroll
    for (int off = 16; off > 0; off >>= 1)
        any |= __shfl_xor_sync(0xFFFFFFFFu, any, off);
    if (t == 0) g_is32 = (any != 0) ? 1 : 0;
}

__device__ __forceinline__ void load_pair(const void* cand, int row,
                                          int is32, int& c0, int& c1) {
    if (is32) {
        const int2 v = ((const int2*)cand)[row];
        c0 = v.x; c1 = v.y;
    } else {
        const longlong2 v = ((const longlong2*)cand)[row];
        c0 = (int)v.x; c1 = (int)v.y;
    }
}

__global__ __launch_bounds__(THREADS)
void contrastive_main(const float4* __restrict__ img,
                      const float4* __restrict__ txt,
                      const void* __restrict__ cand_img,
                      const void* __restrict__ cand_txt,
                      float* __restrict__ out) {
    const int row = blockIdx.x;
    const int t   = threadIdx.x;
    const int is32 = g_is32;

    int a0, a1, b0, b1;
    load_pair(cand_img, row, is32, a0, a1);
    load_pair(cand_txt, row, is32, b0, b1);
    a0 &= (BATCH - 1); a1 &= (BATCH - 1); b0 &= (BATCH - 1); b1 &= (BATCH - 1);

    const float4* ir = img + (size_t)row * ROW_F4;
    const float4* tr = txt + (size_t)row * ROW_F4;

    float4 iv0 = ir[t], iv1 = ir[t + THREADS];
    float4 tv0 = tr[t], tv1 = tr[t + THREADS];

    float acc[11];
    acc[0] = dot4(iv0, iv0) + dot4(iv1, iv1);          // ||img||^2
    acc[1] = dot4(tv0, tv0) + dot4(tv1, tv1);          // ||text||^2
    acc[2] = dot4(iv0, tv0) + dot4(iv1, tv1);          // img.text

    {   // img candidates (anchor = text) -> t2i side
        const float4* g = img + (size_t)a0 * ROW_F4;
        float4 g0 = g[t], g1 = g[t + THREADS];
        acc[3] = dot4(tv0, g0) + dot4(tv1, g1);
        acc[4] = dot4(g0, g0) + dot4(g1, g1);
    }
    {
        const float4* g = img + (size_t)a1 * ROW_F4;
        float4 g0 = g[t], g1 = g[t + THREADS];
        acc[5] = dot4(tv0, g0) + dot4(tv1, g1);
        acc[6] = dot4(g0, g0) + dot4(g1, g1);
    }
    {   // text candidates (anchor = img) -> i2t side
        const float4* g = txt + (size_t)b0 * ROW_F4;
        float4 g0 = g[t], g1 = g[t + THREADS];
        acc[7] = dot4(iv0, g0) + dot4(iv1, g1);
        acc[8] = dot4(g0, g0) + dot4(g1, g1);
    }
    {
        const float4* g = txt + (size_t)b1 * ROW_F4;
        float4 g0 = g[t], g1 = g[t + THREADS];
        acc[9]  = dot4(iv0, g0) + dot4(iv1, g1);
        acc[10] = dot4(g0, g0) + dot4(g1, g1);
    }

    #pragma unroll
    for (int k = 0; k < 11; k++) {
        float v = acc[k];
        #pragma unroll
        for (int off = 16; off > 0; off >>= 1)
            v += __shfl_xor_sync(0xFFFFFFFFu, v, off);
        acc[k] = v;
    }

    __shared__ float s[THREADS / 32][11];
    __shared__ unsigned s_last;
    const int lane = t & 31, warp = t >> 5;
    if (lane == 0) {
        #pragma unroll
        for (int k = 0; k < 11; k++) s[warp][k] = acc[k];
    }
    __syncthreads();

    if (t == 0) {
        float r[11];
        #pragma unroll
        for (int k = 0; k < 11; k++) {
            float v = 0.f;
            #pragma unroll
            for (int w = 0; w < THREADS / 32; w++) v += s[w][k];
            r[k] = v;
        }

        const float n_i = sqrtf(r[0]);
        const float n_t = sqrtf(r[1]);
        const float prod = n_i * n_t;
        const float pos_dist = 1.0f - r[2] / fmaxf(prod, EPSV);
        const float cosv = r[2] / prod;

        const float dA0 = 1.0f - r[3] / fmaxf(n_t * sqrtf(r[4]), EPSV);
        const float dA1 = 1.0f - r[5] / fmaxf(n_t * sqrtf(r[6]), EPSV);
        const float t2i_neg = (dA1 <= dA0) ? dA1 : dA0;

        const float dB0 = 1.0f - r[7] / fmaxf(n_i * sqrtf(r[8]), EPSV);
        const float dB1 = 1.0f - r[9] / fmaxf(n_i * sqrtf(r[10]), EPSV);
        const float i2t_neg = (dB1 <= dB0) ? dB1 : dB0;

        const float i2t_loss = fmaxf(pos_dist - i2t_neg + MARGINV, 0.0f);
        const float t2i_loss = fmaxf(pos_dist - t2i_neg + MARGINV, 0.0f);

        out[1 + row]         = cosv;   // i2t_cosine
        out[1 + BATCH + row] = cosv;   // t2i_cosine (same symmetric formula)
        g_loss[row] = make_float2(i2t_loss, t2i_loss);

        // last-block-arrives handshake
        __threadfence();
        s_last = atomicAdd(&g_done, 1u);
    }
    __syncthreads();

    if (s_last == (unsigned)(gridDim.x - 1)) {
        // This is the last block: g_loss fully written & visible. Reduce it.
        // Fixed-order sum -> bit-deterministic across replays.
        float si = 0.f, st = 0.f;
        #pragma unroll
        for (int i = t; i < BATCH; i += THREADS) {
            float2 v = g_loss[i];
            si += v.x;
            st += v.y;
        }
        #pragma unroll
        for (int off = 16; off > 0; off >>= 1) {
            si += __shfl_xor_sync(0xFFFFFFFFu, si, off);
            st += __shfl_xor_sync(0xFFFFFFFFu, st, off);
        }
        __shared__ float ssi[THREADS / 32], sst[THREADS / 32];
        if (lane == 0) { ssi[warp] = si; sst[warp] = st; }
        __syncthreads();
        if (t == 0) {
            float a = 0.f, b = 0.f;
            #pragma unroll
            for (int w = 0; w < THREADS / 32; w++) { a += ssi[w]; b += sst[w]; }
            out[0] = a / (float)BATCH + b / (float)BATCH;
            g_done = 0;   // reset for next graph replay (deterministic)
        }
    }
}

extern "C" void kernel_launch(void* const* d_in, const int* in_sizes, int n_in,
                              void* d_out, int out_size) {
    const float4* img = (const float4*)d_in[0];
    const float4* txt = (const float4*)d_in[1];
    // d_in[2] = labels (unused), d_in[3] = locations (unused)
    const void* cand_img = d_in[4];
    const void* cand_txt = d_in[5];
    float* out = (float*)d_out;

    detect_dtype<<<1, 32>>>((const unsigned*)cand_img, (const unsigned*)cand_txt);
    contrastive_main<<<BATCH, THREADS>>>(img, txt, cand_img, cand_txt, out);
}

// round 4
// speedup vs baseline: 1.3059x; 1.3059x over previous
#include <cuda_runtime.h>
#include <cuda_bf16.h>
#include <cstdint>

#define BATCH 8192
#define DIM   2048
#define EPSV  1e-8f
#define MARGINV 0.2f

static constexpr int THREADS = 256;
static constexpr int ROW_F4  = DIM / 4;   // 512

__device__ float2 g_loss[BATCH];
__device__ int    g_is32;   // 1 if cand arrays are int32, 0 if int64

__device__ __forceinline__ float dot4(float4 a, float4 b) {
    return a.x * b.x + a.y * b.y + a.z * b.z + a.w * b.w;
}

// Probe index dtype with ONE warp / one batched load round-trip.
// int64 data (values < 8192): every odd 32-bit word is 0.
// int32 data: odd words are random ids; P(all 64 == 0) ~ 8192^-64.
__global__ void detect_dtype(const unsigned* __restrict__ c0,
                             const unsigned* __restrict__ c1) {
    const int t = threadIdx.x;               // 32 threads
    unsigned any = c0[2 * t + 1] | c1[2 * t + 1];
    #pragma unroll
    for (int off = 16; off > 0; off >>= 1)
        any |= __shfl_xor_sync(0xFFFFFFFFu, any, off);
    if (t == 0) g_is32 = (any != 0) ? 1 : 0;
}

__global__ __launch_bounds__(THREADS)
void contrastive_main(const float4* __restrict__ img,
                      const float4* __restrict__ txt,
                      const void* __restrict__ cand_img,
                      const void* __restrict__ cand_txt,
                      float* __restrict__ out) {
    const int row = blockIdx.x;
    const int t   = threadIdx.x;
    const int is32 = g_is32;

    int a0, a1, b0, b1;
    if (is32) {
        const int2 va = ((const int2*)cand_img)[row];
        const int2 vb = ((const int2*)cand_txt)[row];
        a0 = va.x; a1 = va.y; b0 = vb.x; b1 = vb.y;
    } else {
        const longlong2 va = ((const longlong2*)cand_img)[row];
        const longlong2 vb = ((const longlong2*)cand_txt)[row];
        a0 = (int)va.x; a1 = (int)va.y; b0 = (int)vb.x; b1 = (int)vb.y;
    }
    a0 &= (BATCH - 1); a1 &= (BATCH - 1); b0 &= (BATCH - 1); b1 &= (BATCH - 1);

    const float4* ir  = img + (size_t)row * ROW_F4;
    const float4* tr  = txt + (size_t)row * ROW_F4;
    const float4* gA0 = img + (size_t)a0 * ROW_F4;
    const float4* gA1 = img + (size_t)a1 * ROW_F4;
    const float4* gB0 = txt + (size_t)b0 * ROW_F4;
    const float4* gB1 = txt + (size_t)b1 * ROW_F4;

    // Issue ALL 12 loads up front for maximum memory-level parallelism.
    float4 iv0 = ir[t],  iv1 = ir[t + THREADS];
    float4 tv0 = tr[t],  tv1 = tr[t + THREADS];
    float4 A00 = gA0[t], A01 = gA0[t + THREADS];
    float4 A10 = gA1[t], A11 = gA1[t + THREADS];
    float4 B00 = gB0[t], B01 = gB0[t + THREADS];
    float4 B10 = gB1[t], B11 = gB1[t + THREADS];

    float acc[11];
    acc[0]  = dot4(iv0, iv0) + dot4(iv1, iv1);   // ||img||^2
    acc[1]  = dot4(tv0, tv0) + dot4(tv1, tv1);   // ||text||^2
    acc[2]  = dot4(iv0, tv0) + dot4(iv1, tv1);   // img.text
    acc[3]  = dot4(tv0, A00) + dot4(tv1, A01);   // text . img[a0]
    acc[4]  = dot4(A00, A00) + dot4(A01, A01);   // ||img[a0]||^2
    acc[5]  = dot4(tv0, A10) + dot4(tv1, A11);
    acc[6]  = dot4(A10, A10) + dot4(A11, A11);
    acc[7]  = dot4(iv0, B00) + dot4(iv1, B01);   // img . text[b0]
    acc[8]  = dot4(B00, B00) + dot4(B01, B01);
    acc[9]  = dot4(iv0, B10) + dot4(iv1, B11);
    acc[10] = dot4(B10, B10) + dot4(B11, B11);

    #pragma unroll
    for (int k = 0; k < 11; k++) {
        float v = acc[k];
        #pragma unroll
        for (int off = 16; off > 0; off >>= 1)
            v += __shfl_xor_sync(0xFFFFFFFFu, v, off);
        acc[k] = v;
    }

    __shared__ float s[THREADS / 32][11];
    const int lane = t & 31, warp = t >> 5;
    if (lane == 0) {
        #pragma unroll
        for (int k = 0; k < 11; k++) s[warp][k] = acc[k];
    }
    __syncthreads();

    if (t == 0) {
        float r[11];
        #pragma unroll
        for (int k = 0; k < 11; k++) {
            float v = 0.f;
            #pragma unroll
            for (int w = 0; w < THREADS / 32; w++) v += s[w][k];
            r[k] = v;
        }

        const float n_i = sqrtf(r[0]);
        const float n_t = sqrtf(r[1]);
        const float prod = n_i * n_t;
        const float pos_dist = 1.0f - r[2] / fmaxf(prod, EPSV);
        const float cosv = r[2] / prod;

        const float dA0 = 1.0f - r[3] / fmaxf(n_t * sqrtf(r[4]), EPSV);
        const float dA1 = 1.0f - r[5] / fmaxf(n_t * sqrtf(r[6]), EPSV);
        const float t2i_neg = (dA1 <= dA0) ? dA1 : dA0;

        const float dB0 = 1.0f - r[7] / fmaxf(n_i * sqrtf(r[8]), EPSV);
        const float dB1 = 1.0f - r[9] / fmaxf(n_i * sqrtf(r[10]), EPSV);
        const float i2t_neg = (dB1 <= dB0) ? dB1 : dB0;

        const float i2t_loss = fmaxf(pos_dist - i2t_neg + MARGINV, 0.0f);
        const float t2i_loss = fmaxf(pos_dist - t2i_neg + MARGINV, 0.0f);

        out[1 + row]         = cosv;   // i2t_cosine
        out[1 + BATCH + row] = cosv;   // t2i_cosine (same symmetric formula)
        g_loss[row] = make_float2(i2t_loss, t2i_loss);
    }
}

__global__ __launch_bounds__(1024)
void contrastive_reduce(float* __restrict__ out) {
    const int t = threadIdx.x;
    const float4* lp = (const float4*)g_loss;   // 4096 float4 = 8192 float2
    float si = 0.f, st = 0.f;
    #pragma unroll
    for (int i = t; i < BATCH / 2; i += 1024) {
        float4 v = lp[i];
        si += v.x + v.z;
        st += v.y + v.w;
    }
    #pragma unroll
    for (int off = 16; off > 0; off >>= 1) {
        si += __shfl_xor_sync(0xFFFFFFFFu, si, off);
        st += __shfl_xor_sync(0xFFFFFFFFu, st, off);
    }
    __shared__ float ssi[32], sst[32];
    const int lane = t & 31, warp = t >> 5;
    if (lane == 0) { ssi[warp] = si; sst[warp] = st; }
    __syncthreads();
    if (t == 0) {
        float a = 0.f, b = 0.f;
        #pragma unroll
        for (int w = 0; w < 32; w++) { a += ssi[w]; b += sst[w]; }
        out[0] = a / (float)BATCH + b / (float)BATCH;
    }
}

extern "C" void kernel_launch(void* const* d_in, const int* in_sizes, int n_in,
                              void* d_out, int out_size) {
    const float4* img = (const float4*)d_in[0];
    const float4* txt = (const float4*)d_in[1];
    // d_in[2] = labels (unused), d_in[3] = locations (unused)
    const void* cand_img = d_in[4];
    const void* cand_txt = d_in[5];
    float* out = (float*)d_out;

    detect_dtype<<<1, 32>>>((const unsigned*)cand_img, (const unsigned*)cand_txt);
    contrastive_main<<<BATCH, THREADS>>>(img, txt, cand_img, cand_txt, out);
    contrastive_reduce<<<1, 1024>>>(out);
}

// round 5
// speedup vs baseline: 1.3937x; 1.0672x over previous
#include <cuda_runtime.h>
#include <cuda_bf16.h>
#include <cstdint>

#define BATCH 8192
#define DIM   2048
#define EPSV  1e-8f
#define MARGINV 0.2f

static constexpr int THREADS = 256;
static constexpr int ROW_F4  = DIM / 4;   // 512

__device__ float2 g_loss[BATCH];

__device__ __forceinline__ float dot4(float4 a, float4 b) {
    return a.x * b.x + a.y * b.y + a.z * b.z + a.w * b.w;
}

__global__ __launch_bounds__(THREADS)
void contrastive_main(const float4* __restrict__ img,
                      const float4* __restrict__ txt,
                      const int2* __restrict__ cand_img,
                      const int2* __restrict__ cand_txt,
                      float* __restrict__ out) {
    const int row = blockIdx.x;
    const int t   = threadIdx.x;

    // cand arrays are int32 (JAX default x64-disabled downcast; proven R1->R2)
    const int2 va = cand_img[row];
    const int2 vb = cand_txt[row];
    const int a0 = va.x & (BATCH - 1), a1 = va.y & (BATCH - 1);
    const int b0 = vb.x & (BATCH - 1), b1 = vb.y & (BATCH - 1);

    const float4* ir  = img + (size_t)row * ROW_F4;
    const float4* tr  = txt + (size_t)row * ROW_F4;
    const float4* gA0 = img + (size_t)a0 * ROW_F4;
    const float4* gA1 = img + (size_t)a1 * ROW_F4;
    const float4* gB0 = txt + (size_t)b0 * ROW_F4;
    const float4* gB1 = txt + (size_t)b1 * ROW_F4;

    // Issue ALL 12 loads up front for maximum memory-level parallelism.
    float4 iv0 = ir[t],  iv1 = ir[t + THREADS];
    float4 tv0 = tr[t],  tv1 = tr[t + THREADS];
    float4 A00 = gA0[t], A01 = gA0[t + THREADS];
    float4 A10 = gA1[t], A11 = gA1[t + THREADS];
    float4 B00 = gB0[t], B01 = gB0[t + THREADS];
    float4 B10 = gB1[t], B11 = gB1[t + THREADS];

    float acc[11];
    acc[0]  = dot4(iv0, iv0) + dot4(iv1, iv1);   // ||img||^2
    acc[1]  = dot4(tv0, tv0) + dot4(tv1, tv1);   // ||text||^2
    acc[2]  = dot4(iv0, tv0) + dot4(iv1, tv1);   // img.text
    acc[3]  = dot4(tv0, A00) + dot4(tv1, A01);   // text . img[a0]
    acc[4]  = dot4(A00, A00) + dot4(A01, A01);   // ||img[a0]||^2
    acc[5]  = dot4(tv0, A10) + dot4(tv1, A11);
    acc[6]  = dot4(A10, A10) + dot4(A11, A11);
    acc[7]  = dot4(iv0, B00) + dot4(iv1, B01);   // img . text[b0]
    acc[8]  = dot4(B00, B00) + dot4(B01, B01);
    acc[9]  = dot4(iv0, B10) + dot4(iv1, B11);
    acc[10] = dot4(B10, B10) + dot4(B11, B11);

    #pragma unroll
    for (int k = 0; k < 11; k++) {
        float v = acc[k];
        #pragma unroll
        for (int off = 16; off > 0; off >>= 1)
            v += __shfl_xor_sync(0xFFFFFFFFu, v, off);
        acc[k] = v;
    }

    __shared__ float s[THREADS / 32][11];
    const int lane = t & 31, warp = t >> 5;
    if (lane == 0) {
        #pragma unroll
        for (int k = 0; k < 11; k++) s[warp][k] = acc[k];
    }
    __syncthreads();

    if (t == 0) {
        float r[11];
        #pragma unroll
        for (int k = 0; k < 11; k++) {
            float v = 0.f;
            #pragma unroll
            for (int w = 0; w < THREADS / 32; w++) v += s[w][k];
            r[k] = v;
        }

        const float n_i = sqrtf(r[0]);
        const float n_t = sqrtf(r[1]);
        const float prod = n_i * n_t;
        const float pos_dist = 1.0f - r[2] / fmaxf(prod, EPSV);
        const float cosv = r[2] / prod;

        const float dA0 = 1.0f - r[3] / fmaxf(n_t * sqrtf(r[4]), EPSV);
        const float dA1 = 1.0f - r[5] / fmaxf(n_t * sqrtf(r[6]), EPSV);
        const float t2i_neg = (dA1 <= dA0) ? dA1 : dA0;

        const float dB0 = 1.0f - r[7] / fmaxf(n_i * sqrtf(r[8]), EPSV);
        const float dB1 = 1.0f - r[9] / fmaxf(n_i * sqrtf(r[10]), EPSV);
        const float i2t_neg = (dB1 <= dB0) ? dB1 : dB0;

        const float i2t_loss = fmaxf(pos_dist - i2t_neg + MARGINV, 0.0f);
        const float t2i_loss = fmaxf(pos_dist - t2i_neg + MARGINV, 0.0f);

        out[1 + row]         = cosv;   // i2t_cosine
        out[1 + BATCH + row] = cosv;   // t2i_cosine (same symmetric formula)
        g_loss[row] = make_float2(i2t_loss, t2i_loss);
    }
}

__global__ __launch_bounds__(1024)
void contrastive_reduce(float* __restrict__ out) {
    const int t = threadIdx.x;
    const float4* lp = (const float4*)g_loss;   // 4096 float4 = 8192 float2
    float si = 0.f, st = 0.f;
    #pragma unroll
    for (int i = t; i < BATCH / 2; i += 1024) {
        float4 v = lp[i];
        si += v.x + v.z;
        st += v.y + v.w;
    }
    #pragma unroll
    for (int off = 16; off > 0; off >>= 1) {
        si += __shfl_xor_sync(0xFFFFFFFFu, si, off);
        st += __shfl_xor_sync(0xFFFFFFFFu, st, off);
    }
    __shared__ float ssi[32], sst[32];
    const int lane = t & 31, warp = t >> 5;
    if (lane == 0) { ssi[warp] = si; sst[warp] = st; }
    __syncthreads();
    if (t == 0) {
        float a = 0.f, b = 0.f;
        #pragma unroll
        for (int w = 0; w < 32; w++) { a += ssi[w]; b += sst[w]; }
        out[0] = a / (float)BATCH + b / (float)BATCH;
    }
}

extern "C" void kernel_launch(void* const* d_in, const int* in_sizes, int n_in,
                              void* d_out, int out_size) {
    const float4* img = (const float4*)d_in[0];
    const float4* txt = (const float4*)d_in[1];
    // d_in[2] = labels (unused), d_in[3] = locations (unused)
    const int2* cand_img = (const int2*)d_in[4];
    const int2* cand_txt = (const int2*)d_in[5];
    float* out = (float*)d_out;

    contrastive_main<<<BATCH, THREADS>>>(img, txt, cand_img, cand_txt, out);
    contrastive_reduce<<<1, 1024>>>(out);
}